// round 2
// baseline (speedup 1.0000x reference)
#include <cuda_runtime.h>
#include <cuda_fp16.h>
#include <mma.h>
#include <stdint.h>

using namespace nvcuda;

// Problem dims
#define BATCH   256
#define TSEQ    1024
#define IN_D    128
#define HID     256
#define OUT_D   128

// Partitioning: 16 batch-groups x 8 unit-groups = 128 CTAs
#define NBG     16      // batch groups
#define NUG     8       // unit groups
#define MB      16      // batch rows per CTA
#define UPC     32      // hidden units per CTA
#define NGATE   4
#define NROWS   (UPC*NGATE)   // 128 gate rows per CTA
#define KDIM    (HID + IN_D)  // 384 combined K
#define KPAD    392           // padded K stride (multiple of 8, 784B rows)
#define ZPAD    132           // padded z stride (floats)
#define NTHREADS 256

// Shared memory layout sizes
#define SW_ELEMS (NROWS*KPAD)         // 50176 halves
#define SA_ELEMS (MB*KPAD)            // 6272 halves
#define SZ_ELEMS (MB*ZPAD)            // 2112 floats
#define SMEM_BYTES ((SW_ELEMS + SA_ELEMS)*2 + (SZ_ELEMS + NROWS)*4)

// Device-global state (allowed scratch)
__device__ __half   g_h[2][BATCH*HID];     // double-buffered hidden state, fp16
__device__ float    g_h32[BATCH*HID];      // fp32 h_T for final projection
__device__ unsigned g_cnt[NBG][32];        // per-batch-group barrier counters (padded lines)

__device__ __forceinline__ float tanh_fast(float x) {
    float e = __expf(2.0f * x);
    return 1.0f - 2.0f / (e + 1.0f);     // saturates correctly for |x| large
}
__device__ __forceinline__ float sigm_fast(float x) {
    return 1.0f / (1.0f + __expf(-x));
}

__global__ void lstm_init_kernel() {
    int i = blockIdx.x * blockDim.x + threadIdx.x;
    // zero g_h[0] (65536 halves = 32768 u32)
    if (i < (BATCH*HID/2)) ((uint32_t*)&g_h[0][0])[i] = 0u;
    if (i < NBG) g_cnt[i][0] = 0u;
}

__global__ void __launch_bounds__(NTHREADS, 1)
lstm_main_kernel(const float* __restrict__ x,
                 const float* __restrict__ Wgx, const float* __restrict__ bgx, const float* __restrict__ Wgh,
                 const float* __restrict__ Wix, const float* __restrict__ bix, const float* __restrict__ Wih,
                 const float* __restrict__ Wfx, const float* __restrict__ bfx, const float* __restrict__ Wfh,
                 const float* __restrict__ Wox, const float* __restrict__ boxp, const float* __restrict__ Woh,
                 const float* __restrict__ Wp, const float* __restrict__ bp,
                 float* __restrict__ out)
{
    extern __shared__ unsigned char smem_raw[];
    __half* sW    = (__half*)smem_raw;                 // [NROWS][KPAD]
    __half* sA    = sW + SW_ELEMS;                     // [MB][KPAD]  (h | x_t)
    float*  sZ    = (float*)(sA + SA_ELEMS);           // [MB][ZPAD]
    float*  sBias = sZ + SZ_ELEMS;                     // [NROWS]

    const int tid  = threadIdx.x;
    const int warp = tid >> 5;
    const int ug   = blockIdx.x % NUG;
    const int bg   = blockIdx.x / NUG;

    // ---- Load weight slice into smem as fp16 (rows: gate*32+u, cols: [Wh(256) | Wx(128)]) ----
    {
        const float* WhA[4] = {Wgh, Wih, Wfh, Woh};
        const float* WxA[4] = {Wgx, Wix, Wfx, Wox};
        #pragma unroll
        for (int g = 0; g < 4; ++g) {
            const float* wh = WhA[g];
            const float* wx = WxA[g];
            for (int idx = tid; idx < UPC*KDIM; idx += NTHREADS) {
                int ul = idx / KDIM;
                int k  = idx - ul*KDIM;
                int n  = g*UPC + ul;
                int ugl = ug*UPC + ul;
                float w = (k < HID) ? wh[ugl*HID + k] : wx[ugl*IN_D + (k - HID)];
                sW[n*KPAD + k] = __float2half_rn(w);
            }
        }
        if (tid < UPC) {
            const float* bxA[4] = {bgx, bix, bfx, boxp};
            #pragma unroll
            for (int g = 0; g < 4; ++g)
                sBias[g*UPC + tid] = bxA[g][ug*UPC + tid];
        }
    }
    __syncthreads();

    // per-thread cell state: thread handles (b0, uu) and (b0+8, uu)
    const int b0 = tid >> 5;       // 0..7
    const int uu = tid & 31;       // 0..31
    float c0 = 0.0f, c1 = 0.0f;

    wmma::fragment<wmma::matrix_a, 16,16,16, __half, wmma::row_major> fa;
    wmma::fragment<wmma::matrix_b, 16,16,16, __half, wmma::col_major> fb;
    wmma::fragment<wmma::accumulator, 16,16,16, float> fc;

    const int n0 = warp * 16;

    for (int t = 0; t < TSEQ; ++t) {
        const int p = t & 1;
        // ---- Load A tile: h part (16x256 fp16) ----
        const __half* hsrc = g_h[p];
        #pragma unroll
        for (int j = 0; j < 2; ++j) {
            int cc  = tid + (j << 8);
            int row = cc >> 5;          // 0..15
            int c8  = cc & 31;          // 8-half chunk within row
            *(uint4*)&sA[row*KPAD + c8*8] =
                *(const uint4*)&hsrc[(bg*MB + row)*HID + c8*8];
        }
        // ---- x_t part (16x128 fp32 -> fp16, cols 256..383) ----
        #pragma unroll
        for (int j = 0; j < 2; ++j) {
            int cc  = tid + (j << 8);
            int row = cc >> 5;
            int c4  = cc & 31;
            float4 v = *(const float4*)&x[(bg*MB + row)*(TSEQ*IN_D) + t*IN_D + c4*4];
            __half2* d = (__half2*)&sA[row*KPAD + HID + c4*4];
            d[0] = __floats2half2_rn(v.x, v.y);
            d[1] = __floats2half2_rn(v.z, v.w);
        }
        __syncthreads();

        // ---- GEMM: z[16 x 128] = A[16 x 384] * W^T ----
        wmma::fill_fragment(fc, 0.0f);
        #pragma unroll
        for (int kk = 0; kk < KDIM/16; ++kk) {
            wmma::load_matrix_sync(fa, sA + kk*16, KPAD);
            wmma::load_matrix_sync(fb, sW + n0*KPAD + kk*16, KPAD);
            wmma::mma_sync(fc, fa, fb, fc);
        }
        wmma::store_matrix_sync(sZ + n0, fc, ZPAD, wmma::mem_row_major);
        __syncthreads();

        // ---- Epilogue: gates, c/h update, publish h (fp16) ----
        __half* hdst = g_h[p ^ 1];
        #pragma unroll
        for (int j = 0; j < 2; ++j) {
            int b = b0 + j*8;
            const float* zr = &sZ[b*ZPAD];
            float zg = zr[uu]          + sBias[uu];
            float zi = zr[UPC   + uu]  + sBias[UPC   + uu];
            float zf = zr[2*UPC + uu]  + sBias[2*UPC + uu];
            float zo = zr[3*UPC + uu]  + sBias[3*UPC + uu];
            float gv = tanh_fast(zg);
            float iv = sigm_fast(zi);
            float fv = sigm_fast(zf);
            float ov = sigm_fast(zo);
            float& c = j ? c1 : c0;
            c = gv*iv + c*fv;
            float h = tanh_fast(c) * ov;
            int gidx = (bg*MB + b)*HID + ug*UPC + uu;
            hdst[gidx] = __float2half_rn(h);
            if (t == TSEQ-1) g_h32[gidx] = h;
        }

        // ---- Batch-group barrier (8 CTAs) ----
        __threadfence();
        __syncthreads();
        if (tid == 0) {
            atomicAdd(&g_cnt[bg][0], 1u);
            unsigned target = (unsigned)(NUG * (t + 1));
            while (*(volatile unsigned*)&g_cnt[bg][0] < target) { }
            __threadfence();
        }
        __syncthreads();
    }

    // ---- Final projection: out = h_T @ Wp^T + bp (fp32), done by ug==0 CTAs ----
    if (ug == 0) {
        const int b     = tid >> 4;          // 0..15
        const int obase = (tid & 15) * 8;    // 0,8,...,120
        float acc[8];
        #pragma unroll
        for (int r = 0; r < 8; ++r) acc[r] = bp[obase + r];
        const float* hrow = &g_h32[(bg*MB + b)*HID];
        for (int k = 0; k < HID; ++k) {
            float hv = hrow[k];
            #pragma unroll
            for (int r = 0; r < 8; ++r)
                acc[r] = fmaf(hv, Wp[(obase + r)*HID + k], acc[r]);
        }
        #pragma unroll
        for (int r = 0; r < 8; ++r)
            out[(bg*MB + b)*OUT_D + obase + r] = acc[r];
    }
}

extern "C" void kernel_launch(void* const* d_in, const int* in_sizes, int n_in,
                              void* d_out, int out_size) {
    const float* x   = (const float*)d_in[0];
    const float* Wgx = (const float*)d_in[1];
    const float* bgx = (const float*)d_in[2];
    const float* Wgh = (const float*)d_in[3];
    const float* Wix = (const float*)d_in[4];
    const float* bix = (const float*)d_in[5];
    const float* Wih = (const float*)d_in[6];
    const float* Wfx = (const float*)d_in[7];
    const float* bfx = (const float*)d_in[8];
    const float* Wfh = (const float*)d_in[9];
    const float* Wox = (const float*)d_in[10];
    const float* box = (const float*)d_in[11];
    const float* Woh = (const float*)d_in[12];
    const float* Wp  = (const float*)d_in[13];
    const float* bp  = (const float*)d_in[14];
    float* out = (float*)d_out;

    static bool attr_set = false;
    if (!attr_set) {
        cudaFuncSetAttribute(lstm_main_kernel,
                             cudaFuncAttributeMaxDynamicSharedMemorySize, SMEM_BYTES);
        attr_set = true;
    }

    lstm_init_kernel<<<128, 256>>>();
    lstm_main_kernel<<<NBG*NUG, NTHREADS, SMEM_BYTES>>>(
        x, Wgx, bgx, Wgh, Wix, bix, Wih, Wfx, bfx, Wfh, Wox, box, Woh, Wp, bp, out);
}